// round 8
// baseline (speedup 1.0000x reference)
#include <cuda_runtime.h>
#include <cuda_bf16.h>

// Problem dims
#define TSTEPS 499
#define BDIM 64
#define NDIM 512
#define DDIM 100
#define ODIM 10
#define KCAT 1536

// RNN kernel config
#define NCTA 128
#define NTHR 256
#define CHUNK 256
#define NCHUNK 6

// Padded SMEM strides (floats)
// slot strides %32==8 -> 4 slots land on distinct bank groups
// RS_STRIDE %32==4 -> 8 consecutive b-rows per warp on distinct bank groups
#define WM1_STRIDE 1544
#define WPMD_STRIDE 1032
#define WS1_STRIDE 520
#define RS_STRIDE 260
#define RS_BUF (BDIM * RS_STRIDE)

typedef unsigned long long u64;

__device__ __forceinline__ u64 fma2(u64 a, u64 b, u64 c) {
  u64 d;
  asm("fma.rn.f32x2 %0, %1, %2, %3;" : "=l"(d) : "l"(a), "l"(b), "l"(c));
  return d;
}
__device__ __forceinline__ float2 unpack2(u64 v) {
  float2 r;
  asm("mov.b64 {%0, %1}, %2;" : "=f"(r.x), "=f"(r.y) : "l"(v));
  return r;
}

// ---------------- device scratch (static; no allocations) ----------------
__device__ float g_U[2][TSTEPS][BDIM][NDIM];   // [0]=pmd drive, [1]=s1 drive (bias folded)
__device__ float g_r[2][BDIM][KCAT];           // ping-pong rcat = [r_m1 | r_pmd | r_s1]
__device__ float g_rm1h[TSTEPS][BDIM][NDIM];   // r_m1 history for deferred output GEMM
__device__ unsigned g_gen;
__device__ unsigned g_count;

// ---------------- init ----------------
__global__ void init_kernel() {
  int tid = blockIdx.x * blockDim.x + threadIdx.x;
  if (tid == 0) { g_gen = 0u; g_count = 0u; }
  float* r0 = &g_r[0][0][0];
  const int total = BDIM * KCAT;
  for (int i = tid; i < total; i += gridDim.x * blockDim.x) r0[i] = 0.0f;
}

// ---------------- time-parallel input projections ----------------
__global__ void input_proj_kernel(const float* __restrict__ X,
                                  const float* __restrict__ W_in_pmd,
                                  const float* __restrict__ W_in_s1,
                                  const float* __restrict__ b_pmd,
                                  const float* __restrict__ b_s1) {
  __shared__ __align__(16) float Xs[32][DDIM];
  __shared__ __align__(16) float Ws[64][DDIM];
  const int tIdx  = blockIdx.x;
  const int y     = blockIdx.y;
  const int reg   = y >> 4;
  const int bhalf = (y >> 3) & 1;
  const int nblk  = y & 7;
  const int b0 = bhalf * 32;
  const int n0 = nblk * 64;
  const float* W    = reg ? W_in_s1 : W_in_pmd;
  const float* bias = reg ? b_s1    : b_pmd;
  const float* Xt = X + (size_t)(tIdx + 1) * (BDIM * DDIM);
  const int tid = threadIdx.x;

  for (int i = tid; i < 32 * DDIM; i += NTHR)
    Xs[i / DDIM][i % DDIM] = Xt[(b0 + i / DDIM) * DDIM + (i % DDIM)];
  for (int i = tid; i < 64 * DDIM; i += NTHR)
    Ws[i / DDIM][i % DDIM] = W[(n0 + i / DDIM) * DDIM + (i % DDIM)];
  __syncthreads();

  const int ty = tid >> 4, tx = tid & 15;
  const int bb = 2 * ty, nn = 4 * tx;
  float acc[2][4];
#pragma unroll
  for (int j = 0; j < 4; j++) {
    float bv = bias[n0 + nn + j];
    acc[0][j] = bv; acc[1][j] = bv;
  }
#pragma unroll
  for (int k = 0; k < DDIM; k += 4) {
    float4 x0 = *(const float4*)&Xs[bb][k];
    float4 x1 = *(const float4*)&Xs[bb + 1][k];
#pragma unroll
    for (int j = 0; j < 4; j++) {
      float4 wv = *(const float4*)&Ws[nn + j][k];
      acc[0][j] += x0.x * wv.x + x0.y * wv.y + x0.z * wv.z + x0.w * wv.w;
      acc[1][j] += x1.x * wv.x + x1.y * wv.y + x1.z * wv.z + x1.w * wv.w;
    }
  }
#pragma unroll
  for (int i2 = 0; i2 < 2; i2++)
#pragma unroll
    for (int j = 0; j < 4; j++)
      g_U[reg][tIdx][b0 + bb + i2][n0 + nn + j] = acc[i2][j];
}

// ---------------- persistent serial RNN core ----------------
__device__ __forceinline__ void cp_chunk(float* dst, const float* src, int tid) {
  // 64 rows x 256 floats (src row stride KCAT) -> smem (row stride RS_STRIDE)
#pragma unroll
  for (int j = 0; j < 16; j++) {
    int i = tid + j * NTHR;          // 0..4095 float4 segments
    int row = i >> 6;                // 64 segments per row
    int seg = i & 63;
    unsigned s = (unsigned)__cvta_generic_to_shared(dst + row * RS_STRIDE + seg * 4);
    const float* g = src + row * KCAT + seg * 4;
    asm volatile("cp.async.cg.shared.global [%0], [%1], 16;\n" :: "r"(s), "l"(g));
  }
}

extern __shared__ float s_mem[];

__global__ void __launch_bounds__(NTHR, 1)
rnn_kernel(const float* __restrict__ W_rec_m1,
           const float* __restrict__ W_rec_pmd,
           const float* __restrict__ W_rec_s1,
           const float* __restrict__ b_m1,
           const float* __restrict__ W_pmd_m1,
           const float* __restrict__ W_s1_m1,
           const float* __restrict__ W_m1_pmd) {
  float* wm1  = s_mem;                       // [4][WM1_STRIDE]  k: rec_m1 | pmd_m1 | s1_m1
  float* wpmd = wm1 + 4 * WM1_STRIDE;        // [4][WPMD_STRIDE] k: m1_pmd | rec_pmd
  float* ws1  = wpmd + 4 * WPMD_STRIDE;      // [4][WS1_STRIDE]  k: rec_s1
  float* rsb  = ws1 + 4 * WS1_STRIDE;        // [2][BDIM][RS_STRIDE]

  const int cta = blockIdx.x;
  const int tid = threadIdx.x;
  const int nbase = cta * 4;

  // cache this CTA's weight slices in SMEM for the whole run
  for (int i = tid; i < 4 * NDIM; i += NTHR) {
    int slot = i >> 9;
    int k = i & 511;
    int n = nbase + slot;
    wm1[slot * WM1_STRIDE + k]          = W_rec_m1[n * NDIM + k];
    wm1[slot * WM1_STRIDE + 512 + k]    = W_pmd_m1[n * NDIM + k];
    wm1[slot * WM1_STRIDE + 1024 + k]   = W_s1_m1[n * NDIM + k];
    wpmd[slot * WPMD_STRIDE + k]        = W_m1_pmd[n * NDIM + k];
    wpmd[slot * WPMD_STRIDE + 512 + k]  = W_rec_pmd[n * NDIM + k];
    ws1[slot * WS1_STRIDE + k]          = W_rec_s1[n * NDIM + k];
  }

  const int b = tid >> 2;      // row 0..63
  const int slot = tid & 3;    // column slot within CTA
  const int col = nbase + slot;
  const float bias_m1 = b_m1[col];
  const float a = 0.1f;
  const float oma = 1.0f - a;
  float x_m1 = 0.0f, x_pmd = 0.0f, x_s1 = 0.0f;
  __syncthreads();

  for (int t = 1; t <= TSTEPS; t++) {
    const float* rprev = &g_r[(t - 1) & 1][0][0];
    const float u_pmd = __ldg(&g_U[0][t - 1][b][col]);
    const float u_s1  = __ldg(&g_U[1][t - 1][b][col]);

    // prime chunk 0
    cp_chunk(rsb, rprev, tid);
    asm volatile("cp.async.commit_group;\n" ::: "memory");

    u64 am01 = 0ull, am23 = 0ull;   // m1 (2x f32x2 chains)
    u64 ap01 = 0ull, ap23 = 0ull;   // pmd
    u64 as01 = 0ull, as23 = 0ull;   // s1

    for (int ch = 0; ch < NCHUNK; ch++) {
      asm volatile("cp.async.wait_group 0;\n" ::: "memory");
      __syncthreads();   // chunk ch visible to all; all done computing ch-1
      if (ch + 1 < NCHUNK) {
        cp_chunk(rsb + ((ch + 1) & 1) * RS_BUF, rprev + (ch + 1) * CHUNK, tid);
        asm volatile("cp.async.commit_group;\n" ::: "memory");
      }

      const float* rrow = rsb + (ch & 1) * RS_BUF + b * RS_STRIDE;
      const float* w1 = wm1 + slot * WM1_STRIDE + ch * CHUNK;
      if (ch < 4) {  // k in [0,1024): m1 + pmd
        const float* w2 = wpmd + slot * WPMD_STRIDE + ch * CHUNK;
#pragma unroll 8
        for (int k = 0; k < CHUNK; k += 4) {
          ulonglong2 rv = *(const ulonglong2*)(rrow + k);
          ulonglong2 v1 = *(const ulonglong2*)(w1 + k);
          ulonglong2 v2 = *(const ulonglong2*)(w2 + k);
          am01 = fma2(rv.x, v1.x, am01);
          am23 = fma2(rv.y, v1.y, am23);
          ap01 = fma2(rv.x, v2.x, ap01);
          ap23 = fma2(rv.y, v2.y, ap23);
        }
      } else {       // k in [1024,1536): m1 + s1
        const float* w2 = ws1 + slot * WS1_STRIDE + (ch - 4) * CHUNK;
#pragma unroll 8
        for (int k = 0; k < CHUNK; k += 4) {
          ulonglong2 rv = *(const ulonglong2*)(rrow + k);
          ulonglong2 v1 = *(const ulonglong2*)(w1 + k);
          ulonglong2 v2 = *(const ulonglong2*)(w2 + k);
          am01 = fma2(rv.x, v1.x, am01);
          am23 = fma2(rv.y, v1.y, am23);
          as01 = fma2(rv.x, v2.x, as01);
          as23 = fma2(rv.y, v2.y, as23);
        }
      }
    }

    float2 m0 = unpack2(am01), m1v = unpack2(am23);
    float2 p0 = unpack2(ap01), p1v = unpack2(ap23);
    float2 s0 = unpack2(as01), s1v = unpack2(as23);
    const float acc_m1  = (m0.x + m0.y) + (m1v.x + m1v.y);
    const float acc_pmd = (p0.x + p0.y) + (p1v.x + p1v.y);
    const float acc_s1  = (s0.x + s0.y) + (s1v.x + s1v.y);

    x_m1  = oma * x_m1  + a * (acc_m1 + bias_m1);
    x_pmd = oma * x_pmd + a * (acc_pmd + u_pmd);
    x_s1  = oma * x_s1  + a * (acc_s1 + u_s1);
    const float r_m1  = tanhf(x_m1);
    const float r_pmd = tanhf(x_pmd);
    const float r_s1r = tanhf(x_s1);

    float* rnext = &g_r[t & 1][0][0];
    rnext[b * KCAT + col]        = r_m1;
    rnext[b * KCAT + 512 + col]  = r_pmd;
    rnext[b * KCAT + 1024 + col] = r_s1r;
    g_rm1h[t - 1][b][col] = r_m1;

    // ---- grid barrier (monotone generation; all 128 CTAs resident) ----
    __threadfence();
    __syncthreads();
    if (tid == 0) {
      unsigned prev = atomicAdd(&g_count, 1u);
      if (prev == (unsigned)NCTA * (unsigned)t - 1u) {
        __threadfence();
        *((volatile unsigned*)&g_gen) = (unsigned)t;
      } else {
        while (*((volatile unsigned*)&g_gen) < (unsigned)t) __nanosleep(32);
        __threadfence();
      }
    }
    __syncthreads();
  }
}

// ---------------- time-parallel output projection ----------------
// grid=TSTEPS, block=640: one (b,o) pair per thread, 4 accumulator chains
#define WOS 516
__global__ void __launch_bounds__(BDIM * ODIM)
output_kernel(const float* __restrict__ W_out, float* __restrict__ out) {
  __shared__ __align__(16) float Ws[ODIM * WOS];
  const int t = blockIdx.x;
  const int tid = threadIdx.x;
  for (int i = tid; i < ODIM * NDIM; i += BDIM * ODIM)
    Ws[(i / NDIM) * WOS + (i % NDIM)] = W_out[i];
  __syncthreads();

  const int b = tid / ODIM, o = tid % ODIM;
  const float* r = &g_rm1h[t][b][0];
  const float* w = Ws + o * WOS;
  float s0 = 0.f, s1 = 0.f, s2 = 0.f, s3 = 0.f;
#pragma unroll 8
  for (int k = 0; k < NDIM; k += 16) {
    float4 r0 = *(const float4*)(r + k);
    float4 r1 = *(const float4*)(r + k + 4);
    float4 r2 = *(const float4*)(r + k + 8);
    float4 r3 = *(const float4*)(r + k + 12);
    float4 w0 = *(const float4*)(w + k);
    float4 w1 = *(const float4*)(w + k + 4);
    float4 w2 = *(const float4*)(w + k + 8);
    float4 w3 = *(const float4*)(w + k + 12);
    s0 += r0.x * w0.x + r0.y * w0.y + r0.z * w0.z + r0.w * w0.w;
    s1 += r1.x * w1.x + r1.y * w1.y + r1.z * w1.z + r1.w * w1.w;
    s2 += r2.x * w2.x + r2.y * w2.y + r2.z * w2.z + r2.w * w2.w;
    s3 += r3.x * w3.x + r3.y * w3.y + r3.z * w3.z + r3.w * w3.w;
  }
  out[t * (BDIM * ODIM) + b * ODIM + o] = (s0 + s1) + (s2 + s3);
}

// ---------------- launch ----------------
extern "C" void kernel_launch(void* const* d_in, const int* in_sizes, int n_in,
                              void* d_out, int out_size) {
  const float* X         = (const float*)d_in[0];
  const float* W_rec_m1  = (const float*)d_in[1];
  const float* W_rec_pmd = (const float*)d_in[2];
  const float* W_rec_s1  = (const float*)d_in[3];
  const float* b_m1      = (const float*)d_in[4];
  const float* b_pmd     = (const float*)d_in[5];
  const float* b_s1      = (const float*)d_in[6];
  const float* W_pmd_m1  = (const float*)d_in[7];
  const float* W_s1_m1   = (const float*)d_in[8];
  const float* W_m1_pmd  = (const float*)d_in[9];
  const float* W_in_pmd  = (const float*)d_in[10];
  const float* W_in_s1   = (const float*)d_in[11];
  const float* W_out     = (const float*)d_in[12];
  float* out = (float*)d_out;

  init_kernel<<<64, 256>>>();

  dim3 gA(TSTEPS, 32);
  input_proj_kernel<<<gA, NTHR>>>(X, W_in_pmd, W_in_s1, b_pmd, b_s1);

  const int smem_bytes =
      (4 * WM1_STRIDE + 4 * WPMD_STRIDE + 4 * WS1_STRIDE + 2 * RS_BUF) * (int)sizeof(float);
  cudaFuncSetAttribute(rnn_kernel, cudaFuncAttributeMaxDynamicSharedMemorySize, smem_bytes);
  rnn_kernel<<<NCTA, NTHR, smem_bytes>>>(W_rec_m1, W_rec_pmd, W_rec_s1, b_m1,
                                         W_pmd_m1, W_s1_m1, W_m1_pmd);

  output_kernel<<<TSTEPS, BDIM * ODIM>>>(W_out, out);
}

// round 9
// speedup vs baseline: 3.5020x; 3.5020x over previous
#include <cuda_runtime.h>
#include <cuda_bf16.h>

// Problem dims
#define TSTEPS 499
#define BDIM 64
#define NDIM 512
#define DDIM 100
#define ODIM 10
#define KCAT 1536

// RNN kernel config
#define NCTA 128
#define NTHR 256
#define KSLICE 192          // virtual-k per warp (8 warps x 192 = 1536)
#define SUBK 32             // k per sub-chunk (1024 boundary = warp5,sub2 start: aligned)
#define NSUB 6
#define RS_SUB (SUBK * BDIM)      // 2048 floats = 8KB

// SMEM weight strides (floats), %32==8 -> col slices on distinct bank groups
#define WM1_STRIDE 1544
#define WPMD_STRIDE 1032
#define WS1_STRIDE 520
// partials: [8 warps][64 b][13] (12 used: m1 c0..3 | pmd c0..3 | s1 c0..3)
#define PROW 13
#define PPLANE (BDIM * PROW)
// W_out smem stride for output phase (reuses partials area)
#define WOS 520

// ---------------- device scratch (static; no allocations) ----------------
__device__ float g_U[2][TSTEPS][BDIM][NDIM];   // [0]=pmd drive, [1]=s1 drive (bias folded)
__device__ float g_r[2][KCAT][BDIM];           // ping-pong rcat, k-major [k][b]
__device__ float g_rm1h[TSTEPS][BDIM][NDIM];   // r_m1 history for deferred output GEMM
__device__ unsigned g_gen;
__device__ unsigned g_count;

// ---------------- setup: init fold + time-parallel input projections ----------------
// grid (TSTEPS, 32). blocks (x<96, y==0) also zero g_r[0]; block (0,0) resets barrier.
__global__ void setup_kernel(const float* __restrict__ X,
                             const float* __restrict__ W_in_pmd,
                             const float* __restrict__ W_in_s1,
                             const float* __restrict__ b_pmd,
                             const float* __restrict__ b_s1) {
  __shared__ __align__(16) float Xs[32][DDIM];
  __shared__ __align__(16) float Ws[64][DDIM];
  const int tIdx = blockIdx.x;
  const int y    = blockIdx.y;
  const int tid  = threadIdx.x;

  // ---- folded init (runs concurrently; rnn_kernel launches after this kernel) ----
  if (y == 0) {
    if (tIdx == 0 && tid == 0) { g_gen = 0u; g_count = 0u; }
    if (tIdx < 96) {
      float* r0 = &g_r[0][0][0];  // KCAT*BDIM = 98304 floats / 96 blocks = 1024 each
      int base = tIdx * 1024;
#pragma unroll
      for (int j = 0; j < 4; j++) r0[base + tid + j * NTHR] = 0.0f;
    }
  }

  const int reg   = y >> 4;
  const int bhalf = (y >> 3) & 1;
  const int nblk  = y & 7;
  const int b0 = bhalf * 32;
  const int n0 = nblk * 64;
  const float* W    = reg ? W_in_s1 : W_in_pmd;
  const float* bias = reg ? b_s1    : b_pmd;
  const float* Xt = X + (size_t)(tIdx + 1) * (BDIM * DDIM);

  for (int i = tid; i < 32 * DDIM; i += NTHR)
    Xs[i / DDIM][i % DDIM] = Xt[(b0 + i / DDIM) * DDIM + (i % DDIM)];
  for (int i = tid; i < 64 * DDIM; i += NTHR)
    Ws[i / DDIM][i % DDIM] = W[(n0 + i / DDIM) * DDIM + (i % DDIM)];
  __syncthreads();

  const int ty = tid >> 4, tx = tid & 15;
  const int bb = 2 * ty, nn = 4 * tx;
  float acc[2][4];
#pragma unroll
  for (int j = 0; j < 4; j++) {
    float bv = bias[n0 + nn + j];
    acc[0][j] = bv; acc[1][j] = bv;
  }
#pragma unroll
  for (int k = 0; k < DDIM; k += 4) {
    float4 x0 = *(const float4*)&Xs[bb][k];
    float4 x1 = *(const float4*)&Xs[bb + 1][k];
#pragma unroll
    for (int j = 0; j < 4; j++) {
      float4 wv = *(const float4*)&Ws[nn + j][k];
      acc[0][j] += x0.x * wv.x + x0.y * wv.y + x0.z * wv.z + x0.w * wv.w;
      acc[1][j] += x1.x * wv.x + x1.y * wv.y + x1.z * wv.z + x1.w * wv.w;
    }
  }
#pragma unroll
  for (int i2 = 0; i2 < 2; i2++)
#pragma unroll
    for (int j = 0; j < 4; j++)
      g_U[reg][tIdx][b0 + bb + i2][n0 + nn + j] = acc[i2][j];
}

// ---------------- persistent serial RNN core (+ fused output projection) ----------------
__device__ __forceinline__ void cp_sub(float* dst, const float* src, int lane) {
  // contiguous 8KB (32 k-rows x 64 b) copy, 16 float4 per lane
#pragma unroll
  for (int j = 0; j < 16; j++) {
    int o = (lane + j * 32) * 4;
    unsigned s = (unsigned)__cvta_generic_to_shared(dst + o);
    asm volatile("cp.async.cg.shared.global [%0], [%1], 16;\n" :: "r"(s), "l"(src + o) : "memory");
  }
}

#define FMA_J(R, WA, WB, VA, VB, AO)                                        \
  am[0][0] = fmaf(R.x, WA, am[0][0]); am[1][0] = fmaf(R.y, WA, am[1][0]);   \
  am[2][0] = fmaf(R.z, WA, am[2][0]); am[3][0] = fmaf(R.w, WA, am[3][0]);   \
  am[0][1] = fmaf(R.x, WB, am[0][1]); am[1][1] = fmaf(R.y, WB, am[1][1]);   \
  am[2][1] = fmaf(R.z, WB, am[2][1]); am[3][1] = fmaf(R.w, WB, am[3][1]);   \
  AO[0][0] = fmaf(R.x, VA, AO[0][0]); AO[1][0] = fmaf(R.y, VA, AO[1][0]);   \
  AO[2][0] = fmaf(R.z, VA, AO[2][0]); AO[3][0] = fmaf(R.w, VA, AO[3][0]);   \
  AO[0][1] = fmaf(R.x, VB, AO[0][1]); AO[1][1] = fmaf(R.y, VB, AO[1][1]);   \
  AO[2][1] = fmaf(R.z, VB, AO[2][1]); AO[3][1] = fmaf(R.w, VB, AO[3][1]);

#define INNER(AO, V1, V2)                                                   \
  _Pragma("unroll 4")                                                       \
  for (int kk = 0; kk < SUBK; kk += 4) {                                    \
    float4 r0 = *(const float4*)(rsc + (kk + 0) * BDIM + bg4);              \
    float4 r1 = *(const float4*)(rsc + (kk + 1) * BDIM + bg4);              \
    float4 r2 = *(const float4*)(rsc + (kk + 2) * BDIM + bg4);              \
    float4 r3 = *(const float4*)(rsc + (kk + 3) * BDIM + bg4);              \
    float4 wa = *(const float4*)(w1a + kk);                                 \
    float4 wb = *(const float4*)(w1b + kk);                                 \
    float4 va = *(const float4*)((V1) + kk);                                \
    float4 vb = *(const float4*)((V2) + kk);                                \
    FMA_J(r0, wa.x, wb.x, va.x, vb.x, AO)                                   \
    FMA_J(r1, wa.y, wb.y, va.y, vb.y, AO)                                   \
    FMA_J(r2, wa.z, wb.z, va.z, vb.z, AO)                                   \
    FMA_J(r3, wa.w, wb.w, va.w, vb.w, AO)                                   \
  }

extern __shared__ float s_mem[];

__global__ void __launch_bounds__(NTHR, 1)
rnn_kernel(const float* __restrict__ W_rec_m1,
           const float* __restrict__ W_rec_pmd,
           const float* __restrict__ W_rec_s1,
           const float* __restrict__ b_m1,
           const float* __restrict__ W_pmd_m1,
           const float* __restrict__ W_s1_m1,
           const float* __restrict__ W_m1_pmd,
           const float* __restrict__ W_out,
           float* __restrict__ out) {
  float* wm1  = s_mem;                       // [4][WM1_STRIDE]  vk: rec_m1 | pmd_m1 | s1_m1
  float* wpmd = wm1 + 4 * WM1_STRIDE;        // [4][WPMD_STRIDE] vk: m1_pmd | rec_pmd
  float* ws1  = wpmd + 4 * WPMD_STRIDE;      // [4][WS1_STRIDE]  vk: rec_s1
  float* rs   = ws1 + 4 * WS1_STRIDE;        // [8 warps][2][SUBK][BDIM]
  float* part = rs + 8 * 2 * RS_SUB;         // [8][BDIM][PROW]

  const int cta = blockIdx.x;
  const int tid = threadIdx.x;
  const int nbase = cta * 4;

  // cache this CTA's weight column slices in SMEM for the whole run
  for (int i = tid; i < 4 * NDIM; i += NTHR) {
    int slot = i >> 9;
    int k = i & 511;
    int n = nbase + slot;
    wm1[slot * WM1_STRIDE + k]          = W_rec_m1[n * NDIM + k];
    wm1[slot * WM1_STRIDE + 512 + k]    = W_pmd_m1[n * NDIM + k];
    wm1[slot * WM1_STRIDE + 1024 + k]   = W_s1_m1[n * NDIM + k];
    wpmd[slot * WPMD_STRIDE + k]        = W_m1_pmd[n * NDIM + k];
    wpmd[slot * WPMD_STRIDE + 512 + k]  = W_rec_pmd[n * NDIM + k];
    ws1[slot * WS1_STRIDE + k]          = W_rec_s1[n * NDIM + k];
  }

  // compute-role mapping: warp owns 192 virtual-k; halves own col pairs; bg owns 4 b-rows
  const int warp = tid >> 5;
  const int lane = tid & 31;
  const int cg = (tid >> 4) & 1;
  const int bg4 = (tid & 15) * 4;
  const int kbase = warp * KSLICE;
  const int ca = cg * 2, cb = cg * 2 + 1;
  float* rs0 = rs + warp * 2 * RS_SUB;

  // state-role mapping: thread owns cell (b, col)
  const int b = tid >> 2;
  const int slot = tid & 3;
  const int col = nbase + slot;
  const float bias_m1 = b_m1[col];
  const float a = 0.1f;
  const float oma = 1.0f - a;
  float x_m1 = 0.0f, x_pmd = 0.0f, x_s1 = 0.0f;
  __syncthreads();

  for (int t = 1; t <= TSTEPS; t++) {
    // issue U loads early (DRAM-streamed; latency hidden by the step's compute)
    const float u_pmd = __ldg(&g_U[0][t - 1][b][col]);
    const float u_s1  = __ldg(&g_U[1][t - 1][b][col]);

    const float* rprev = &g_r[(t - 1) & 1][0][0];   // [k][b]

    // prime first two sub-chunks (warp-local double buffer, no CTA syncs in mainloop)
    cp_sub(rs0, rprev + (size_t)kbase * BDIM, lane);
    asm volatile("cp.async.commit_group;\n" ::: "memory");
    cp_sub(rs0 + RS_SUB, rprev + (size_t)(kbase + SUBK) * BDIM, lane);
    asm volatile("cp.async.commit_group;\n" ::: "memory");

    float am[4][2] = {{0.f, 0.f}, {0.f, 0.f}, {0.f, 0.f}, {0.f, 0.f}};
    float ap[4][2] = {{0.f, 0.f}, {0.f, 0.f}, {0.f, 0.f}, {0.f, 0.f}};
    float as_[4][2] = {{0.f, 0.f}, {0.f, 0.f}, {0.f, 0.f}, {0.f, 0.f}};

#pragma unroll 1
    for (int s = 0; s < NSUB; s++) {
      if (s < NSUB - 1) { asm volatile("cp.async.wait_group 1;\n" ::: "memory"); }
      else              { asm volatile("cp.async.wait_group 0;\n" ::: "memory"); }

      const int k0 = kbase + s * SUBK;
      const float* rsc = rs0 + (s & 1) * RS_SUB;
      const float* w1a = wm1 + ca * WM1_STRIDE + k0;
      const float* w1b = wm1 + cb * WM1_STRIDE + k0;
      if (k0 < 1024) {   // sub-chunks never straddle the 1024 boundary (192*5+64=1024)
        const float* v1 = wpmd + ca * WPMD_STRIDE + k0;
        const float* v2 = wpmd + cb * WPMD_STRIDE + k0;
        INNER(ap, v1, v2)
      } else {
        const float* v1 = ws1 + ca * WS1_STRIDE + (k0 - 1024);
        const float* v2 = ws1 + cb * WS1_STRIDE + (k0 - 1024);
        INNER(as_, v1, v2)
      }
      if (s + 2 < NSUB) {
        cp_sub(rs0 + (s & 1) * RS_SUB, rprev + (size_t)(k0 + 2 * SUBK) * BDIM, lane);
        asm volatile("cp.async.commit_group;\n" ::: "memory");
      }
    }

    // write k-slice partials
    {
      float* p0 = part + warp * PPLANE + bg4 * PROW;
#pragma unroll
      for (int row = 0; row < 4; row++) {
        float* p = p0 + row * PROW;
        p[ca]     = am[row][0];  p[cb]     = am[row][1];
        p[4 + ca] = ap[row][0];  p[4 + cb] = ap[row][1];
        p[8 + ca] = as_[row][0]; p[8 + cb] = as_[row][1];
      }
    }
    __syncthreads();

    // reduce over 8 k-slices + leaky update + tanh (state role)
    float sm = 0.f, sp = 0.f, ss = 0.f;
#pragma unroll
    for (int q = 0; q < 8; q++) {
      const float* p = part + q * PPLANE + b * PROW;
      sm += p[slot]; sp += p[4 + slot]; ss += p[8 + slot];
    }
    x_m1  = oma * x_m1  + a * (sm + bias_m1);
    x_pmd = oma * x_pmd + a * (sp + u_pmd);
    x_s1  = oma * x_s1  + a * (ss + u_s1);
    const float r_m1  = tanhf(x_m1);
    const float r_pmd = tanhf(x_pmd);
    const float r_s1v = tanhf(x_s1);

    float* rn = &g_r[t & 1][0][0];
    rn[col * BDIM + b]          = r_m1;
    rn[(512 + col) * BDIM + b]  = r_pmd;
    rn[(1024 + col) * BDIM + b] = r_s1v;
    g_rm1h[t - 1][b][col] = r_m1;

    // ---- grid barrier (monotone generation; all 128 CTAs resident) ----
    __threadfence();
    __syncthreads();
    if (tid == 0) {
      unsigned prev = atomicAdd(&g_count, 1u);
      if (prev == (unsigned)NCTA * (unsigned)t - 1u) {
        __threadfence();
        *((volatile unsigned*)&g_gen) = (unsigned)t;
      } else {
        while (*((volatile unsigned*)&g_gen) < (unsigned)t) __nanosleep(32);
        __threadfence();
      }
    }
    __syncthreads();
  }

  // ---------------- fused output projection: out[t] = r_m1[t] @ W_out^T ----------------
  float* wo = part;   // reuse partials area: ODIM*WOS = 5200 <= 6656 floats
  for (int i = tid; i < ODIM * NDIM; i += NTHR)
    wo[(i / NDIM) * WOS + (i % NDIM)] = W_out[i];
  __syncthreads();

  for (int t = cta; t < TSTEPS; t += NCTA) {
    const float* R = &g_rm1h[t][0][0];
    for (int idx = tid; idx < BDIM * ODIM; idx += NTHR) {
      int bb = idx / ODIM, o = idx % ODIM;
      const float* r = R + bb * NDIM;
      const float* w = wo + o * WOS;
      float s0 = 0.f, s1 = 0.f, s2 = 0.f, s3 = 0.f;
#pragma unroll 8
      for (int k = 0; k < NDIM; k += 16) {
        float4 r0 = *(const float4*)(r + k);
        float4 r1 = *(const float4*)(r + k + 4);
        float4 r2 = *(const float4*)(r + k + 8);
        float4 r3 = *(const float4*)(r + k + 12);
        float4 w0 = *(const float4*)(w + k);
        float4 w1 = *(const float4*)(w + k + 4);
        float4 w2 = *(const float4*)(w + k + 8);
        float4 w3 = *(const float4*)(w + k + 12);
        s0 += r0.x * w0.x + r0.y * w0.y + r0.z * w0.z + r0.w * w0.w;
        s1 += r1.x * w1.x + r1.y * w1.y + r1.z * w1.z + r1.w * w1.w;
        s2 += r2.x * w2.x + r2.y * w2.y + r2.z * w2.z + r2.w * w2.w;
        s3 += r3.x * w3.x + r3.y * w3.y + r3.z * w3.z + r3.w * w3.w;
      }
      out[t * (BDIM * ODIM) + idx] = (s0 + s1) + (s2 + s3);
    }
  }
}

// ---------------- launch (2 kernels per call -> ncu -s 5 -c 1 lands on rnn_kernel) ----------------
extern "C" void kernel_launch(void* const* d_in, const int* in_sizes, int n_in,
                              void* d_out, int out_size) {
  (void)in_sizes; (void)n_in; (void)out_size;
  const float* X         = (const float*)d_in[0];
  const float* W_rec_m1  = (const float*)d_in[1];
  const float* W_rec_pmd = (const float*)d_in[2];
  const float* W_rec_s1  = (const float*)d_in[3];
  const float* b_m1      = (const float*)d_in[4];
  const float* b_pmd     = (const float*)d_in[5];
  const float* b_s1      = (const float*)d_in[6];
  const float* W_pmd_m1  = (const float*)d_in[7];
  const float* W_s1_m1   = (const float*)d_in[8];
  const float* W_m1_pmd  = (const float*)d_in[9];
  const float* W_in_pmd  = (const float*)d_in[10];
  const float* W_in_s1   = (const float*)d_in[11];
  const float* W_out     = (const float*)d_in[12];
  float* out = (float*)d_out;

  dim3 gA(TSTEPS, 32);
  setup_kernel<<<gA, NTHR>>>(X, W_in_pmd, W_in_s1, b_pmd, b_s1);

  const int smem_bytes =
      (4 * WM1_STRIDE + 4 * WPMD_STRIDE + 4 * WS1_STRIDE + 8 * 2 * RS_SUB + 8 * PPLANE) *
      (int)sizeof(float);   // 207,232 B
  cudaFuncSetAttribute(rnn_kernel, cudaFuncAttributeMaxDynamicSharedMemorySize, smem_bytes);
  rnn_kernel<<<NCTA, NTHR, smem_bytes>>>(W_rec_m1, W_rec_pmd, W_rec_s1, b_m1,
                                         W_pmd_m1, W_s1_m1, W_m1_pmd, W_out, out);
}